// round 12
// baseline (speedup 1.0000x reference)
#include <cuda_runtime.h>
#include <math.h>

// Elman RNN, fp32. B=128, S=1024, I=256, H=512, O=256, N_TARGETS=1.
// Phase A: P[t][j][b] fma2-packed GEMM (R5, measured 721us).
// Phase B: R4 persistent k-split recurrence, inner loop converted to fma2
//          over b-pairs (identical numerics, half the FMA issues).
// Phase C: output projection + hidden emit (R4 verbatim).

typedef unsigned long long ull;

namespace {
constexpr int S = 1024, B = 128, I = 256, H = 512, O = 256;
constexpr int G = 128;    // persistent grid
constexpr int KT = 16;    // k chunks
constexpr int KC = 32;    // chunk size
constexpr int JC = 128;   // j tile
}

__device__ float g_P[(size_t)S * H * B];      // [t][j][b] pre-activations
__device__ float g_Ht[H * B];                 // hidden state [k][b]
__device__ float g_Part[(size_t)KT * H * B];  // k-split partials [kk][j][b]
__device__ unsigned g_arrive;                 // grid barrier counter

__device__ __forceinline__ ull pack2(float x) {
    ull r;
    asm("mov.b64 %0, {%1, %1};" : "=l"(r) : "f"(x));
    return r;
}
__device__ __forceinline__ float2 unpack2(ull v) {
    float2 r;
    asm("mov.b64 {%0, %1}, %2;" : "=f"(r.x), "=f"(r.y) : "l"(v));
    return r;
}
__device__ __forceinline__ void fma2(ull& d, ull a, ull b) {
    asm("fma.rn.f32x2 %0, %1, %2, %0;" : "+l"(d) : "l"(a), "l"(b));
}

__device__ __forceinline__ void grid_barrier(unsigned target) {
    __syncthreads();
    if (threadIdx.x == 0) {
        __threadfence();
        atomicAdd(&g_arrive, 1u);
        unsigned v;
        do {
            asm volatile("ld.acquire.gpu.u32 %0, [%1];"
                         : "=r"(v) : "l"(&g_arrive) : "memory");
        } while (v < target);
    }
    __syncthreads();
}

// ---------------- Phase A: pre-activation GEMM (fma2, R5 verbatim) ----------
// grid (S, H/128), 256 threads. CTA: 128 j x 128 b for one t, K=I=256.
__global__ void __launch_bounds__(256) phaseA_kernel(
    const float* __restrict__ seq, const float* __restrict__ Wi2h,
    const float* __restrict__ bi2h) {
    const int t = blockIdx.x;
    const int j0 = blockIdx.y * 128;
    const int tid = threadIdx.x;
    const int tx = tid & 15;   // 8 b per thread
    const int ty = tid >> 4;   // 8 j per thread (4 fma2 pairs)
    __shared__ float sh_a[16 * 132];  // [k][j], padded
    __shared__ float sh_b[16 * 132];  // [k][b], padded
    ull acc[4][8];
#pragma unroll
    for (int r = 0; r < 4; r++)
#pragma unroll
        for (int c = 0; c < 8; c++) acc[r][c] = 0;

    for (int k0 = 0; k0 < I; k0 += 16) {
        __syncthreads();
#pragma unroll
        for (int q = 0; q < 2; q++) {
            int idx = tid + q * 256;  // 0..511
            int j = idx >> 2, kq = idx & 3;
            float4 v = *(const float4*)(Wi2h + (size_t)(j0 + j) * (I + H) + k0 + kq * 4);
            sh_a[(kq * 4 + 0) * 132 + j] = v.x;
            sh_a[(kq * 4 + 1) * 132 + j] = v.y;
            sh_a[(kq * 4 + 2) * 132 + j] = v.z;
            sh_a[(kq * 4 + 3) * 132 + j] = v.w;
        }
#pragma unroll
        for (int q = 0; q < 2; q++) {
            int idx = tid + q * 256;
            int b = idx >> 2, kq = idx & 3;
            float4 v = *(const float4*)(seq + (size_t)b * (S * I) + (size_t)t * I + k0 + kq * 4);
            sh_b[(kq * 4 + 0) * 132 + b] = v.x;
            sh_b[(kq * 4 + 1) * 132 + b] = v.y;
            sh_b[(kq * 4 + 2) * 132 + b] = v.z;
            sh_b[(kq * 4 + 3) * 132 + b] = v.w;
        }
        __syncthreads();
#pragma unroll
        for (int k = 0; k < 16; k++) {
            ulonglong2 a01 = *(const ulonglong2*)(sh_a + k * 132 + ty * 8);
            ulonglong2 a23 = *(const ulonglong2*)(sh_a + k * 132 + ty * 8 + 4);
            float4 b0 = *(const float4*)(sh_b + k * 132 + tx * 8);
            float4 b1 = *(const float4*)(sh_b + k * 132 + tx * 8 + 4);
            ull bb[8] = {pack2(b0.x), pack2(b0.y), pack2(b0.z), pack2(b0.w),
                         pack2(b1.x), pack2(b1.y), pack2(b1.z), pack2(b1.w)};
#pragma unroll
            for (int c = 0; c < 8; c++) {
                fma2(acc[0][c], a01.x, bb[c]);
                fma2(acc[1][c], a01.y, bb[c]);
                fma2(acc[2][c], a23.x, bb[c]);
                fma2(acc[3][c], a23.y, bb[c]);
            }
        }
    }
    // epilogue: unpack j-pairs, add bias, write P[t][j][b]
#pragma unroll
    for (int r = 0; r < 4; r++) {
        int j = j0 + ty * 8 + r * 2;
        float bj0 = bi2h[j], bj1 = bi2h[j + 1];
        float lo[8], hi[8];
#pragma unroll
        for (int c = 0; c < 8; c++) {
            float2 f = unpack2(acc[r][c]);
            lo[c] = f.x + bj0;
            hi[c] = f.y + bj1;
        }
        float* op0 = g_P + (size_t)t * (H * B) + (size_t)j * B + tx * 8;
        float* op1 = op0 + B;
        *(float4*)op0 = make_float4(lo[0], lo[1], lo[2], lo[3]);
        *(float4*)(op0 + 4) = make_float4(lo[4], lo[5], lo[6], lo[7]);
        *(float4*)op1 = make_float4(hi[0], hi[1], hi[2], hi[3]);
        *(float4*)(op1 + 4) = make_float4(hi[4], hi[5], hi[6], hi[7]);
    }
}

// ---------------- Phase B: R4 skeleton, fma2 inner loop ----------------
// 128 CTAs = 2 batch-halves x 4 j-tiles(128) x 16 k-chunks(32).
// Per step: stage1 partial GEMM -> barrier -> stage2 reduce+tanh -> barrier.
__global__ void __launch_bounds__(256) phaseB_kernel(const float* __restrict__ Wi2h) {
    const int cta = blockIdx.x;
    const int kk = cta & 15;
    const int jj = (cta >> 4) & 3;
    const int bb = cta >> 6;
    const int k0 = kk * KC;
    const int j0 = jj * JC;
    const int b0 = bb * 64;
    const int tid = threadIdx.x;
    const int tx = tid & 15;  // 4 b per thread (2 fma2 pairs)
    const int ty = tid >> 4;  // 8 j per thread
    __shared__ float sh_w[KC * JC];  // [k][j] 16KB, persistent across steps
    __shared__ float sh_h[KC * 64];  // [k][b] 8KB, restaged each step

    // Load Wh tile once: Wh[k][j] = Wi2h[(j0+j)*(I+H) + I + k0 + k]
#pragma unroll
    for (int q = 0; q < 4; q++) {
        int idx = tid + q * 256;  // 0..1023
        int j = idx >> 3, kq = idx & 7;
        float4 v = *(const float4*)(Wi2h + (size_t)(j0 + j) * (I + H) + I + k0 + kq * 4);
        sh_w[(kq * 4 + 0) * JC + j] = v.x;
        sh_w[(kq * 4 + 1) * JC + j] = v.y;
        sh_w[(kq * 4 + 2) * JC + j] = v.z;
        sh_w[(kq * 4 + 3) * JC + j] = v.w;
    }

    unsigned bar = 0;
    for (int t = 0; t < S; t++) {
        // stage 1: stage h chunk [k0..k0+32) x [b0..b0+64) into smem
#pragma unroll
        for (int q = 0; q < 2; q++) {
            int idx = tid + q * 256;  // 0..511
            int k = idx >> 4, bq = idx & 15;
            *(float4*)(sh_h + k * 64 + bq * 4) =
                *(const float4*)(g_Ht + (k0 + k) * B + b0 + bq * 4);
        }
        __syncthreads();

        // fma2 over b-pairs: acc2[p][c] = (b_{2p}, b_{2p+1}) for j = ty*8+c
        ull acc2[2][8];
#pragma unroll
        for (int p = 0; p < 2; p++)
#pragma unroll
            for (int c = 0; c < 8; c++) acc2[p][c] = 0;
#pragma unroll 8
        for (int k = 0; k < KC; k++) {
            ulonglong2 hp = *(const ulonglong2*)(sh_h + k * 64 + tx * 4);
            float4 wv0 = *(const float4*)(sh_w + k * JC + ty * 8);
            float4 wv1 = *(const float4*)(sh_w + k * JC + ty * 8 + 4);
            ull ww[8] = {pack2(wv0.x), pack2(wv0.y), pack2(wv0.z), pack2(wv0.w),
                         pack2(wv1.x), pack2(wv1.y), pack2(wv1.z), pack2(wv1.w)};
#pragma unroll
            for (int c = 0; c < 8; c++) {
                fma2(acc2[0][c], ww[c], hp.x);
                fma2(acc2[1][c], ww[c], hp.y);
            }
        }
        {
            float* pp = g_Part + (size_t)kk * (H * B) + (size_t)(j0 + ty * 8) * B + b0 + tx * 4;
#pragma unroll
            for (int c = 0; c < 8; c++) {
                ulonglong2 v;
                v.x = acc2[0][c];
                v.y = acc2[1][c];
                *(ulonglong2*)(pp + c * B) = v;  // same bytes as R4's float4
            }
        }
        grid_barrier(++bar * G);

        // stage 2: reduce KT partials + pre-activation, tanh, write new Ht
        {
            int o = cta * 512 + tid;
            const float* pP = g_P + (size_t)t * (H * B);
            float a0 = pP[o];
            float a1 = pP[o + 256];
#pragma unroll
            for (int q = 0; q < KT; q++) {
                a0 += g_Part[(size_t)q * (H * B) + o];
                a1 += g_Part[(size_t)q * (H * B) + o + 256];
            }
            g_Ht[o] = tanhf(a0);
            g_Ht[o + 256] = tanhf(a1);
        }
        grid_barrier(++bar * G);
    }
}

// ---------------- Phase C: output projection + hidden emit (R4) -------------
__global__ void __launch_bounds__(256) phaseC_kernel(
    const float* __restrict__ Wh2o, const float* __restrict__ bh2o,
    float* __restrict__ out, int out_size) {
    int idx = blockIdx.x * 256 + threadIdx.x;  // 0..32767
    int b = idx >> 8, o = idx & 255;
    float acc = bh2o[o];
    const float4* wrow = (const float4*)(Wh2o + (size_t)o * H);
#pragma unroll 4
    for (int k4 = 0; k4 < H / 4; k4++) {
        float4 w = wrow[k4];
        int kb = k4 * 4;
        acc = fmaf(g_Ht[(kb + 0) * B + b], w.x, acc);
        acc = fmaf(g_Ht[(kb + 1) * B + b], w.y, acc);
        acc = fmaf(g_Ht[(kb + 2) * B + b], w.z, acc);
        acc = fmaf(g_Ht[(kb + 3) * B + b], w.w, acc);
    }
    if (idx < out_size) out[idx] = acc;  // output (B,1,O): idx = b*256+o
    if (out_size >= B * O + B * H) {
#pragma unroll
        for (int q = 0; q < 2; q++) {
            int e = idx + q * (B * O);  // 0..65535
            int hb = e >> 9, hk = e & 511;
            out[B * O + e] = g_Ht[hk * B + hb];
        }
    }
}

extern "C" void kernel_launch(void* const* d_in, const int* in_sizes, int n_in,
                              void* d_out, int out_size) {
    const float* seq  = (const float*)d_in[0];
    const float* Wi2h = (const float*)d_in[1];
    const float* bi2h = (const float*)d_in[2];
    const float* Wh2o = (const float*)d_in[3];
    const float* bh2o = (const float*)d_in[4];
    float* out = (float*)d_out;

    void* pArr = nullptr;
    cudaGetSymbolAddress(&pArr, g_arrive);
    cudaMemsetAsync(pArr, 0, sizeof(unsigned), 0);
    void* pHt = nullptr;
    cudaGetSymbolAddress(&pHt, g_Ht);
    cudaMemsetAsync(pHt, 0, (size_t)H * B * sizeof(float), 0);

    phaseA_kernel<<<dim3(S, H / 128), 256>>>(seq, Wi2h, bi2h);
    phaseB_kernel<<<G, 256>>>(Wi2h);
    phaseC_kernel<<<(B * O) / 256, 256>>>(Wh2o, bh2o, out, out_size);
}